// round 8
// baseline (speedup 1.0000x reference)
#include <cuda_runtime.h>
#include <math.h>

// Sinkhorn distance, N=M=4096, D=256, EPS=0.1, 100 iterations.
// R8: cost matrix stored as int16 fixed-point (1/7 log2-unit resolution)
// around a runtime base, in BOTH row-major and transposed layouts (64 MB
// total, L2-resident). u- and v-passes are identical warp-per-row sweeps
// with warp-local reductions only. Log2-scaled math throughout.

#define NN 4096
#define KK 256
#define SCALEF 14.4269504088896340736f   // log2(e)/EPS
#define NEG_BIG (-1e30f)
#define THREADS 1024
#define NBMAX 160
#define N_ITER 100
#define QS  7.0f
#define QSI (1.0f / 7.0f)

__device__ __align__(16) short g_Ci [(size_t)NN * NN];   // 32 MB: row-major quantized C2
__device__ __align__(16) short g_CiT[(size_t)NN * NN];   // 32 MB: transposed
__device__ __align__(16) float g_u[NN];
__device__ __align__(16) float g_v[NN];
__device__ float g_xs[NN];
__device__ float g_ys[NN];
__device__ float g_qbase;                                 // BASE in C2 (log2) units
__device__ double g_dpart[NBMAX];

__device__ unsigned g_bar_count;
__device__ volatile unsigned g_bar_gen;

__device__ __forceinline__ float ex2f(float x) {
    float r; asm("ex2.approx.ftz.f32 %0, %1;" : "=f"(r) : "f"(x)); return r;
}
__device__ __forceinline__ float lg2f(float x) {
    float r; asm("lg2.approx.ftz.f32 %0, %1;" : "=f"(r) : "f"(x)); return r;
}

__device__ __forceinline__ void grid_sync(int NB) {
    __syncthreads();
    if (threadIdx.x == 0) {
        unsigned gen = g_bar_gen;
        __threadfence();
        unsigned t = atomicAdd(&g_bar_count, 1u);
        if (t == (unsigned)(NB - 1)) {
            g_bar_count = 0;
            __threadfence();
            g_bar_gen = gen + 1;
        } else {
            while (g_bar_gen == gen) { }
        }
        __threadfence();
    }
    __syncthreads();
}

// online-LSE pairwise merge of (m,s) across the warp (5 shfl steps)
__device__ __forceinline__ void warp_lse_merge(float& m, float& s) {
    #pragma unroll
    for (int o = 16; o; o >>= 1) {
        float m2 = __shfl_xor_sync(0xffffffffu, m, o);
        float s2 = __shfl_xor_sync(0xffffffffu, s, o);
        float M = fmaxf(m, m2);
        s = s * ex2f(m - M) + s2 * ex2f(m2 - M);
        m = M;
    }
}

// warp-per-row LSE sweep over a quantized 4096-elem row.
// returns -(lse) on lane 0. vs = (dual potential - BASE) cached in smem.
__device__ __forceinline__ float row_neg_lse(const short* Crow, const float* vs, int lane) {
    const int4* Cp = (const int4*)Crow + lane;      // 8 shorts per int4
    float m0 = NEG_BIG, s0 = 0.f;
    float m1 = NEG_BIG, s1 = 0.f;
    #pragma unroll
    for (int r = 0; r < 16; ++r) {
        union { int4 v; short s[8]; } U;
        U.v = __ldg(Cp + (r << 5));
        const float* vp = vs + (r << 8) + (lane << 3);
        float4 V0 = *(const float4*)vp;
        float4 V1 = *(const float4*)(vp + 4);
        float t0 = fmaf((float)U.s[0], -QSI, V0.x);
        float t1 = fmaf((float)U.s[1], -QSI, V0.y);
        float t2 = fmaf((float)U.s[2], -QSI, V0.z);
        float t3 = fmaf((float)U.s[3], -QSI, V0.w);
        float t4 = fmaf((float)U.s[4], -QSI, V1.x);
        float t5 = fmaf((float)U.s[5], -QSI, V1.y);
        float t6 = fmaf((float)U.s[6], -QSI, V1.z);
        float t7 = fmaf((float)U.s[7], -QSI, V1.w);
        float mc = fmaxf(fmaxf(fmaxf(t0, t1), fmaxf(t2, t3)),
                         fmaxf(fmaxf(t4, t5), fmaxf(t6, t7)));
        if (r & 1) {
            float mn = fmaxf(m1, mc);
            float e = ((ex2f(t0 - mn) + ex2f(t1 - mn)) + (ex2f(t2 - mn) + ex2f(t3 - mn)))
                    + ((ex2f(t4 - mn) + ex2f(t5 - mn)) + (ex2f(t6 - mn) + ex2f(t7 - mn)));
            s1 = s1 * ex2f(m1 - mn) + e;
            m1 = mn;
        } else {
            float mn = fmaxf(m0, mc);
            float e = ((ex2f(t0 - mn) + ex2f(t1 - mn)) + (ex2f(t2 - mn) + ex2f(t3 - mn)))
                    + ((ex2f(t4 - mn) + ex2f(t5 - mn)) + (ex2f(t6 - mn) + ex2f(t7 - mn)));
            s0 = s0 * ex2f(m0 - mn) + e;
            m0 = mn;
        }
    }
    float M = fmaxf(m0, m1);
    float s = s0 * ex2f(m0 - M) + s1 * ex2f(m1 - M);
    warp_lse_merge(M, s);
    return -(M + lg2f(s));
}

// ---------------------------------------------------------------------------
__global__ __launch_bounds__(256) void sqnorm_kernel(const float* __restrict__ X,
                                                     const float* __restrict__ Y) {
    int gw = (blockIdx.x * 256 + threadIdx.x) >> 5;
    int lane = threadIdx.x & 31;
    const float* src = (gw < NN) ? (X + (size_t)gw * KK) : (Y + (size_t)(gw - NN) * KK);
    float s = 0.f;
    #pragma unroll
    for (int c = 0; c < KK; c += 32) {
        float a = src[c + lane];
        s = fmaf(a, a, s);
    }
    #pragma unroll
    for (int o = 16; o; o >>= 1) s += __shfl_xor_sync(0xffffffffu, s, o);
    if (lane == 0) {
        if (gw < NN) g_xs[gw] = s; else g_ys[gw - NN] = s;
    }
}

// base = SCALEF * (mean(|x|^2) + mean(|y|^2))  (single block)
__global__ __launch_bounds__(1024) void base_kernel() {
    int tid = threadIdx.x;
    float s = 0.f;
    for (int i = tid; i < NN; i += 1024) s += g_xs[i] + g_ys[i];
    __shared__ float red[32];
    #pragma unroll
    for (int o = 16; o; o >>= 1) s += __shfl_xor_sync(0xffffffffu, s, o);
    if ((tid & 31) == 0) red[tid >> 5] = s;
    __syncthreads();
    if (tid < 32) {
        float t = red[tid];
        #pragma unroll
        for (int o = 16; o; o >>= 1) t += __shfl_xor_sync(0xffffffffu, t, o);
        if (tid == 0) g_qbase = SCALEF * (t / (float)NN);
    }
    if (tid == 0) { g_bar_count = 0; g_bar_gen = 0; }
    for (int i = tid; i < NN; i += 1024) g_v[i] = 0.f;
}

// ---------------------------------------------------------------------------
// GEMM: C2 = (|x|^2 + |y|^2 - 2 x.y) * SCALEF, quantized to int16 around base,
// written in both layouts.
__global__ __launch_bounds__(256) void gemm_kernel(const float* __restrict__ X,
                                                   const float* __restrict__ Y) {
    __shared__ float As[8][128];
    __shared__ float Bs[8][128];
    const int tid = threadIdx.x;
    const int bx = blockIdx.x;
    const int by = blockIdx.y;
    const int ar = tid >> 1;
    const int ak = (tid & 1) * 4;
    const int tx = tid & 15;
    const int ty = tid >> 4;

    const float* xp = X + (size_t)(by * 128 + ar) * KK + ak;
    const float* yp = Y + (size_t)(bx * 128 + ar) * KK + ak;

    float acc[8][8];
    #pragma unroll
    for (int i = 0; i < 8; ++i)
        #pragma unroll
        for (int j = 0; j < 8; ++j) acc[i][j] = 0.f;

    for (int kt = 0; kt < KK; kt += 8) {
        float4 av = *(const float4*)(xp + kt);
        float4 bv = *(const float4*)(yp + kt);
        __syncthreads();
        As[ak + 0][ar] = av.x; As[ak + 1][ar] = av.y;
        As[ak + 2][ar] = av.z; As[ak + 3][ar] = av.w;
        Bs[ak + 0][ar] = bv.x; Bs[ak + 1][ar] = bv.y;
        Bs[ak + 2][ar] = bv.z; Bs[ak + 3][ar] = bv.w;
        __syncthreads();
        #pragma unroll
        for (int k = 0; k < 8; ++k) {
            float a[8], b[8];
            *(float4*)(a)     = *(const float4*)&As[k][ty * 8];
            *(float4*)(a + 4) = *(const float4*)&As[k][ty * 8 + 4];
            *(float4*)(b)     = *(const float4*)&Bs[k][tx * 8];
            *(float4*)(b + 4) = *(const float4*)&Bs[k][tx * 8 + 4];
            #pragma unroll
            for (int i = 0; i < 8; ++i)
                #pragma unroll
                for (int j = 0; j < 8; ++j)
                    acc[i][j] = fmaf(a[i], b[j], acc[i][j]);
        }
    }

    const int gi0 = by * 128 + ty * 8;
    const int gj0 = bx * 128 + tx * 8;
    const float qb = g_qbase;
    float yv[8];
    #pragma unroll
    for (int j = 0; j < 8; ++j) yv[j] = g_ys[gj0 + j];

    short q[8][8];
    #pragma unroll
    for (int i = 0; i < 8; ++i) {
        float xs = g_xs[gi0 + i];
        #pragma unroll
        for (int j = 0; j < 8; ++j) {
            float c2 = (xs + yv[j] - 2.f * acc[i][j]) * SCALEF;
            float qf = (c2 - qb) * QS;
            qf = fminf(fmaxf(qf, -32600.f), 32600.f);
            q[i][j] = (short)__float2int_rn(qf);
        }
    }
    // row-major store: 8 shorts contiguous per row
    #pragma unroll
    for (int i = 0; i < 8; ++i)
        *(int4*)&g_Ci[(size_t)(gi0 + i) * NN + gj0] = *(int4*)&q[i][0];
    // transposed store: for each col j, 8 shorts (over i) contiguous
    #pragma unroll
    for (int j = 0; j < 8; ++j) {
        short qt[8];
        #pragma unroll
        for (int i = 0; i < 8; ++i) qt[i] = q[i][j];
        *(int4*)&g_CiT[(size_t)(gj0 + j) * NN + gi0] = *(int4*)&qt[0];
    }
}

// ---------------------------------------------------------------------------
__global__ __launch_bounds__(THREADS, 1) void sinkhorn_persistent(int NB, float* __restrict__ out) {
    const int tid = threadIdx.x;
    const int bid = blockIdx.x;
    const int lane = tid & 31;
    const int wid = tid >> 5;
    const float qb = g_qbase;

    __shared__ float svec[NN];          // 16 KB: shifted dual potential cache
    __shared__ float sred[32];

    for (int it = 0; it < N_ITER; ++it) {
        // ---- u-pass: warp-per-row over g_Ci ----
        for (int i = tid; i < NN; i += THREADS) svec[i] = g_v[i] - qb;
        __syncthreads();
        for (int row = bid + wid * NB; row < NN; row += 32 * NB) {
            float r = row_neg_lse(g_Ci + (size_t)row * NN, svec, lane);
            if (lane == 0) g_u[row] = r;
        }
        grid_sync(NB);

        // ---- v-pass: warp-per-column over g_CiT (identical sweep) ----
        for (int i = tid; i < NN; i += THREADS) svec[i] = g_u[i] - qb;
        __syncthreads();
        for (int col = bid + wid * NB; col < NN; col += 32 * NB) {
            float r = row_neg_lse(g_CiT + (size_t)col * NN, svec, lane);
            if (lane == 0) g_v[col] = r;
        }
        grid_sync(NB);
    }

    // ---- final cost: sum P*C / N  (warp-per-row over g_Ci) ----
    {
        for (int i = tid; i < NN; i += THREADS) svec[i] = g_v[i] - qb;
        __syncthreads();
        float acc = 0.f;
        for (int row = bid + wid * NB; row < NN; row += 32 * NB) {
            const float u2 = g_u[row];
            const int4* Cp = (const int4*)(g_Ci + (size_t)row * NN) + lane;
            #pragma unroll
            for (int r = 0; r < 16; ++r) {
                union { int4 v; short s[8]; } U;
                U.v = __ldg(Cp + (r << 5));
                const float* vp = svec + (r << 8) + (lane << 3);
                #pragma unroll
                for (int k = 0; k < 8; ++k) {
                    float fq = (float)U.s[k];
                    float arg = fmaf(fq, -QSI, u2 + vp[k]);
                    float c2v = fmaf(fq, QSI, qb);
                    acc = fmaf(ex2f(arg), c2v, acc);
                }
            }
        }
        #pragma unroll
        for (int o = 16; o; o >>= 1) acc += __shfl_xor_sync(0xffffffffu, acc, o);
        __syncthreads();
        if (lane == 0) sred[wid] = acc;
        __syncthreads();
        if (wid == 0) {
            float s = sred[lane];
            #pragma unroll
            for (int o = 16; o; o >>= 1) s += __shfl_xor_sync(0xffffffffu, s, o);
            if (lane == 0) g_dpart[bid] = (double)s;
        }
        grid_sync(NB);
        if (bid == 0 && tid == 0) {
            double S = 0.0;
            for (int b = 0; b < NB; ++b) S += g_dpart[b];
            out[0] = (float)(S / ((double)SCALEF * (double)NN));
        }
    }
}

// ---------------------------------------------------------------------------
extern "C" void kernel_launch(void* const* d_in, const int* in_sizes, int n_in,
                              void* d_out, int out_size) {
    const float* x = (const float*)d_in[0];
    const float* y = (const float*)d_in[1];
    float* out = (float*)d_out;

    int dev = 0;
    cudaGetDevice(&dev);
    int sm = 148;
    cudaDeviceGetAttribute(&sm, cudaDevAttrMultiProcessorCount, dev);
    int NB = sm < NBMAX ? sm : NBMAX;

    sqnorm_kernel<<<1024, 256>>>(x, y);
    base_kernel<<<1, 1024>>>();
    gemm_kernel<<<dim3(32, 32), 256>>>(x, y);
    sinkhorn_persistent<<<NB, THREADS>>>(NB, out);
}

// round 9
// speedup vs baseline: 1.0852x; 1.0852x over previous
#include <cuda_runtime.h>
#include <math.h>

// Sinkhorn distance, N=M=4096, D=256, EPS=0.1, 100 iterations.
// R9: fp32, persistent single-wave kernel, 512 threads/CTA (128-reg budget).
// u-pass: warp-per-row with depth-3 group pipeline (8 LDG.128 in flight/warp),
// branchless dual-stream online LSE. v-pass: 16 strata, half-warp merges.

#define NN 4096
#define KK 256
#define SCALEF 14.4269504088896340736f   // log2(e)/EPS
#define NEG_BIG (-1e30f)
#define THREADS 512
#define NBMAX 160
#define N_ITER 100

__device__ __align__(16) float g_C2[(size_t)NN * NN];     // 64 MB: C * SCALEF
__device__ __align__(16) float g_u[NN];
__device__ __align__(16) float g_v[NN];
__device__ float g_xs[NN];
__device__ float g_ys[NN];
__device__ double g_dpart[NBMAX];

__device__ unsigned g_bar_count;
__device__ volatile unsigned g_bar_gen;

__device__ __forceinline__ float ex2f(float x) {
    float r; asm("ex2.approx.ftz.f32 %0, %1;" : "=f"(r) : "f"(x)); return r;
}
__device__ __forceinline__ float lg2f(float x) {
    float r; asm("lg2.approx.ftz.f32 %0, %1;" : "=f"(r) : "f"(x)); return r;
}

__device__ __forceinline__ void grid_sync(int NB) {
    __syncthreads();
    if (threadIdx.x == 0) {
        unsigned gen = g_bar_gen;
        __threadfence();
        unsigned t = atomicAdd(&g_bar_count, 1u);
        if (t == (unsigned)(NB - 1)) {
            g_bar_count = 0;
            __threadfence();
            g_bar_gen = gen + 1;
        } else {
            while (g_bar_gen == gen) { }
        }
        __threadfence();
    }
    __syncthreads();
}

// online-LSE pairwise merge across the full warp
__device__ __forceinline__ void warp_lse_merge(float& m, float& s) {
    #pragma unroll
    for (int o = 16; o; o >>= 1) {
        float m2 = __shfl_xor_sync(0xffffffffu, m, o);
        float s2 = __shfl_xor_sync(0xffffffffu, s, o);
        float M = fmaxf(m, m2);
        s = s * ex2f(m - M) + s2 * ex2f(m2 - M);
        m = M;
    }
}

// ---------------------------------------------------------------------------
__global__ __launch_bounds__(256) void sqnorm_kernel(const float* __restrict__ X,
                                                     const float* __restrict__ Y) {
    int gw = (blockIdx.x * 256 + threadIdx.x) >> 5;
    int lane = threadIdx.x & 31;
    const float* src = (gw < NN) ? (X + (size_t)gw * KK) : (Y + (size_t)(gw - NN) * KK);
    float s = 0.f;
    #pragma unroll
    for (int c = 0; c < KK; c += 32) {
        float a = src[c + lane];
        s = fmaf(a, a, s);
    }
    #pragma unroll
    for (int o = 16; o; o >>= 1) s += __shfl_xor_sync(0xffffffffu, s, o);
    if (lane == 0) {
        if (gw < NN) g_xs[gw] = s; else g_ys[gw - NN] = s;
    }
}

__global__ void init_kernel() {
    int i = blockIdx.x * 256 + threadIdx.x;
    if (i < NN) g_v[i] = 0.f;
    if (i == 0) { g_bar_count = 0; g_bar_gen = 0; }
}

// ---------------------------------------------------------------------------
// C2[i][j] = (|x_i|^2 + |y_j|^2 - 2 x_i . y_j) * SCALEF  (fp32 FFMA GEMM)
__global__ __launch_bounds__(256) void gemm_kernel(const float* __restrict__ X,
                                                   const float* __restrict__ Y) {
    __shared__ float As[8][128];
    __shared__ float Bs[8][128];
    const int tid = threadIdx.x;
    const int bx = blockIdx.x;
    const int by = blockIdx.y;
    const int ar = tid >> 1;
    const int ak = (tid & 1) * 4;
    const int tx = tid & 15;
    const int ty = tid >> 4;

    const float* xp = X + (size_t)(by * 128 + ar) * KK + ak;
    const float* yp = Y + (size_t)(bx * 128 + ar) * KK + ak;

    float acc[8][8];
    #pragma unroll
    for (int i = 0; i < 8; ++i)
        #pragma unroll
        for (int j = 0; j < 8; ++j) acc[i][j] = 0.f;

    for (int kt = 0; kt < KK; kt += 8) {
        float4 av = *(const float4*)(xp + kt);
        float4 bv = *(const float4*)(yp + kt);
        __syncthreads();
        As[ak + 0][ar] = av.x; As[ak + 1][ar] = av.y;
        As[ak + 2][ar] = av.z; As[ak + 3][ar] = av.w;
        Bs[ak + 0][ar] = bv.x; Bs[ak + 1][ar] = bv.y;
        Bs[ak + 2][ar] = bv.z; Bs[ak + 3][ar] = bv.w;
        __syncthreads();
        #pragma unroll
        for (int k = 0; k < 8; ++k) {
            float a[8], b[8];
            *(float4*)(a)     = *(const float4*)&As[k][ty * 8];
            *(float4*)(a + 4) = *(const float4*)&As[k][ty * 8 + 4];
            *(float4*)(b)     = *(const float4*)&Bs[k][tx * 8];
            *(float4*)(b + 4) = *(const float4*)&Bs[k][tx * 8 + 4];
            #pragma unroll
            for (int i = 0; i < 8; ++i)
                #pragma unroll
                for (int j = 0; j < 8; ++j)
                    acc[i][j] = fmaf(a[i], b[j], acc[i][j]);
        }
    }

    const int gi0 = by * 128 + ty * 8;
    const int gj0 = bx * 128 + tx * 8;
    float yv[8];
    #pragma unroll
    for (int j = 0; j < 8; ++j) yv[j] = g_ys[gj0 + j];
    #pragma unroll
    for (int i = 0; i < 8; ++i) {
        float xs = g_xs[gi0 + i];
        float4 o0, o1;
        o0.x = (xs + yv[0] - 2.f * acc[i][0]) * SCALEF;
        o0.y = (xs + yv[1] - 2.f * acc[i][1]) * SCALEF;
        o0.z = (xs + yv[2] - 2.f * acc[i][2]) * SCALEF;
        o0.w = (xs + yv[3] - 2.f * acc[i][3]) * SCALEF;
        o1.x = (xs + yv[4] - 2.f * acc[i][4]) * SCALEF;
        o1.y = (xs + yv[5] - 2.f * acc[i][5]) * SCALEF;
        o1.z = (xs + yv[6] - 2.f * acc[i][6]) * SCALEF;
        o1.w = (xs + yv[7] - 2.f * acc[i][7]) * SCALEF;
        float* dst = g_C2 + (size_t)(gi0 + i) * NN + gj0;
        *(float4*)(dst)     = o0;
        *(float4*)(dst + 4) = o1;
    }
}

// ---------------------------------------------------------------------------
// process one 16-elem group (4 float4 chunks) into dual online-LSE streams
__device__ __forceinline__ void lse_group(const float4* __restrict__ cur,
                                          const float4* __restrict__ Vp, int base4,
                                          float& m0, float& s0, float& m1, float& s1) {
    float4 Va = Vp[(base4 + 0) << 5];
    float4 Vb = Vp[(base4 + 1) << 5];
    float4 Vc = Vp[(base4 + 2) << 5];
    float4 Vd = Vp[(base4 + 3) << 5];
    {
        float t0 = Va.x - cur[0].x, t1 = Va.y - cur[0].y;
        float t2 = Va.z - cur[0].z, t3 = Va.w - cur[0].w;
        float t4 = Vb.x - cur[1].x, t5 = Vb.y - cur[1].y;
        float t6 = Vb.z - cur[1].z, t7 = Vb.w - cur[1].w;
        float mc = fmaxf(fmaxf(fmaxf(t0, t1), fmaxf(t2, t3)),
                         fmaxf(fmaxf(t4, t5), fmaxf(t6, t7)));
        float mn = fmaxf(m0, mc);
        float e = ((ex2f(t0 - mn) + ex2f(t1 - mn)) + (ex2f(t2 - mn) + ex2f(t3 - mn)))
                + ((ex2f(t4 - mn) + ex2f(t5 - mn)) + (ex2f(t6 - mn) + ex2f(t7 - mn)));
        s0 = s0 * ex2f(m0 - mn) + e;
        m0 = mn;
    }
    {
        float t0 = Vc.x - cur[2].x, t1 = Vc.y - cur[2].y;
        float t2 = Vc.z - cur[2].z, t3 = Vc.w - cur[2].w;
        float t4 = Vd.x - cur[3].x, t5 = Vd.y - cur[3].y;
        float t6 = Vd.z - cur[3].z, t7 = Vd.w - cur[3].w;
        float mc = fmaxf(fmaxf(fmaxf(t0, t1), fmaxf(t2, t3)),
                         fmaxf(fmaxf(t4, t5), fmaxf(t6, t7)));
        float mn = fmaxf(m1, mc);
        float e = ((ex2f(t0 - mn) + ex2f(t1 - mn)) + (ex2f(t2 - mn) + ex2f(t3 - mn)))
                + ((ex2f(t4 - mn) + ex2f(t5 - mn)) + (ex2f(t6 - mn) + ex2f(t7 - mn)));
        s1 = s1 * ex2f(m1 - mn) + e;
        m1 = mn;
    }
}

__global__ __launch_bounds__(THREADS, 1) void sinkhorn_persistent(int NB, float* __restrict__ out) {
    const int tid = threadIdx.x;
    const int bid = blockIdx.x;
    const int lane = tid & 31;
    const int wid = tid >> 5;                     // 0..15

    __shared__ float svec[NN];                    // 16 KB dual-potential cache
    __shared__ float sm_m[16][33];
    __shared__ float sm_s[16][33];
    __shared__ float sred[16];

    for (int it = 0; it < N_ITER; ++it) {
        // ---- u-pass: warp-per-row, depth-3 group pipeline ----
        for (int i = tid; i < NN; i += THREADS) svec[i] = g_v[i];
        __syncthreads();

        for (int row = bid + wid * NB; row < NN; row += 16 * NB) {
            const float4* Cp = (const float4*)(g_C2 + (size_t)row * NN) + lane;
            const float4* Vp = (const float4*)svec + lane;
            float m0 = NEG_BIG, s0 = 0.f, m1 = NEG_BIG, s1 = 0.f;
            float4 buf[3][4];
            #pragma unroll
            for (int k = 0; k < 4; ++k) buf[0][k] = __ldg(Cp + ((0 + k) << 5));
            #pragma unroll
            for (int k = 0; k < 4; ++k) buf[1][k] = __ldg(Cp + ((4 + k) << 5));
            #pragma unroll
            for (int g = 0; g < 8; ++g) {
                if (g + 2 < 8) {
                    #pragma unroll
                    for (int k = 0; k < 4; ++k)
                        buf[(g + 2) % 3][k] = __ldg(Cp + (((g + 2) * 4 + k) << 5));
                }
                lse_group(buf[g % 3], Vp, g * 4, m0, s0, m1, s1);
            }
            float M = fmaxf(m0, m1);
            float s = s0 * ex2f(m0 - M) + s1 * ex2f(m1 - M);
            warp_lse_merge(M, s);
            if (lane == 0) g_u[row] = -(M + lg2f(s));
        }
        grid_sync(NB);

        // ---- v-pass: CTA owns 32 columns; 16 strata; half-warp merges ----
        for (int i = tid; i < NN; i += THREADS) svec[i] = g_u[i];
        __syncthreads();
        for (int g = bid; g < NN / 32; g += NB) {
            const int c = lane;
            const int r = wid;                    // stratum 0..15
            const int col = (g << 5) + c;
            float m = NEG_BIG, s = 0.f;
            for (int q0 = 0; q0 < NN; q0 += 256) {
                const float* p = g_C2 + (size_t)(q0 + r) * NN + col;
                const float* up = &svec[q0 + r];
                float t[16];
                #pragma unroll
                for (int k = 0; k < 16; ++k)
                    t[k] = up[k << 4] - __ldg(p + ((size_t)k << 4) * NN);
                float mc = t[0];
                #pragma unroll
                for (int k = 1; k < 16; ++k) mc = fmaxf(mc, t[k]);
                float mn = fmaxf(m, mc);
                float e[16];
                #pragma unroll
                for (int k = 0; k < 16; ++k) e[k] = ex2f(t[k] - mn);
                #pragma unroll
                for (int o = 1; o < 16; o <<= 1)
                    #pragma unroll
                    for (int k = 0; k < 16; k += 2 * o) e[k] += e[k + o];
                s = s * ex2f(m - mn) + e[0];
                m = mn;
            }
            sm_m[r][c] = m;
            sm_s[r][c] = s;
            __syncthreads();
            {   // warp w merges 16 strata for columns 2w (lanes 0-15) and 2w+1 (16-31)
                int cc = 2 * wid + (lane >> 4);
                int st = lane & 15;
                float mm = sm_m[st][cc];
                float ss = sm_s[st][cc];
                #pragma unroll
                for (int o = 8; o; o >>= 1) {
                    float m2 = __shfl_xor_sync(0xffffffffu, mm, o);
                    float s2 = __shfl_xor_sync(0xffffffffu, ss, o);
                    float M = fmaxf(mm, m2);
                    ss = ss * ex2f(mm - M) + s2 * ex2f(m2 - M);
                    mm = M;
                }
                if (st == 0) g_v[(g << 5) + cc] = -(mm + lg2f(ss));
            }
            __syncthreads();
        }
        grid_sync(NB);
    }

    // ---- final cost: sum P*C / N  (warp-per-row) ----
    {
        for (int i = tid; i < NN; i += THREADS) svec[i] = g_v[i];
        __syncthreads();
        float acc = 0.f;
        for (int row = bid + wid * NB; row < NN; row += 16 * NB) {
            const float u2 = g_u[row];
            const float* Crow = g_C2 + (size_t)row * NN;
            #pragma unroll 4
            for (int c0 = 0; c0 < NN; c0 += 128) {
                int cc = c0 + lane * 4;
                float4 C4 = __ldg((const float4*)(Crow + cc));
                float4 V4 = *(const float4*)&svec[cc];
                acc = fmaf(ex2f(u2 + V4.x - C4.x), C4.x, acc);
                acc = fmaf(ex2f(u2 + V4.y - C4.y), C4.y, acc);
                acc = fmaf(ex2f(u2 + V4.z - C4.z), C4.z, acc);
                acc = fmaf(ex2f(u2 + V4.w - C4.w), C4.w, acc);
            }
        }
        #pragma unroll
        for (int o = 16; o; o >>= 1) acc += __shfl_xor_sync(0xffffffffu, acc, o);
        __syncthreads();
        if (lane == 0) sred[wid] = acc;
        __syncthreads();
        if (tid < 16) {
            float s = sred[tid];
            #pragma unroll
            for (int o = 8; o; o >>= 1) s += __shfl_xor_sync(0x0000ffffu, s, o);
            if (tid == 0) g_dpart[bid] = (double)s;
        }
        grid_sync(NB);
        if (bid == 0 && tid == 0) {
            double S = 0.0;
            for (int b = 0; b < NB; ++b) S += g_dpart[b];
            out[0] = (float)(S / ((double)SCALEF * (double)NN));
        }
    }
}

// ---------------------------------------------------------------------------
extern "C" void kernel_launch(void* const* d_in, const int* in_sizes, int n_in,
                              void* d_out, int out_size) {
    const float* x = (const float*)d_in[0];
    const float* y = (const float*)d_in[1];
    float* out = (float*)d_out;

    int dev = 0;
    cudaGetDevice(&dev);
    int sm = 148;
    cudaDeviceGetAttribute(&sm, cudaDevAttrMultiProcessorCount, dev);
    int NB = sm < NBMAX ? sm : NBMAX;

    sqnorm_kernel<<<1024, 256>>>(x, y);
    init_kernel<<<16, 256>>>();
    gemm_kernel<<<dim3(32, 32), 256>>>(x, y);
    sinkhorn_persistent<<<NB, THREADS>>>(NB, out);
}

// round 11
// speedup vs baseline: 1.2328x; 1.1360x over previous
#include <cuda_runtime.h>
#include <math.h>

// Sinkhorn distance, N=M=4096, D=256, EPS=0.1, 100 iterations.
// R10: lazy LSE. Shift = previous iteration's row/col max; warp-chunks whose
// max is below shift-40 skip the exp block entirely (warp-vote, uniform).
// Validity guard: shift-10 <= m_run <= shift+50, else retry with exact max.
// Skipped terms are < 2^-30 relative -> exact to fp32. R5 skeleton otherwise.

#define NN 4096
#define KK 256
#define SCALEF 14.4269504088896340736f   // log2(e)/EPS
#define NEG_BIG (-1e30f)
#define THREADS 1024
#define NBMAX 160
#define N_ITER 100
#define TH_SKIP 40.f
#define TH_LO   10.f
#define TH_HI   50.f
#define CLAMP   80.f

__device__ __align__(16) float g_C2[(size_t)NN * NN];     // 64 MB: C * SCALEF
__device__ __align__(16) float g_u[NN];
__device__ __align__(16) float g_v[NN];
__device__ __align__(16) float g_mu[NN];                  // row max estimate (t-domain)
__device__ __align__(16) float g_mv[NN];                  // col max estimate
__device__ float g_xs[NN];
__device__ float g_ys[NN];
__device__ double g_dpart[NBMAX];

__device__ unsigned g_bar_count;
__device__ volatile unsigned g_bar_gen;

__device__ __forceinline__ float ex2f(float x) {
    float r; asm("ex2.approx.ftz.f32 %0, %1;" : "=f"(r) : "f"(x)); return r;
}
__device__ __forceinline__ float lg2f(float x) {
    float r; asm("lg2.approx.ftz.f32 %0, %1;" : "=f"(r) : "f"(x)); return r;
}

__device__ __forceinline__ void grid_sync(int NB) {
    __syncthreads();
    if (threadIdx.x == 0) {
        unsigned gen = g_bar_gen;
        __threadfence();
        unsigned t = atomicAdd(&g_bar_count, 1u);
        if (t == (unsigned)(NB - 1)) {
            g_bar_count = 0;
            __threadfence();
            g_bar_gen = gen + 1;
        } else {
            while (g_bar_gen == gen) { }
        }
        __threadfence();
    }
    __syncthreads();
}

// ---------------------------------------------------------------------------
__global__ __launch_bounds__(256) void sqnorm_kernel(const float* __restrict__ X,
                                                     const float* __restrict__ Y) {
    int gw = (blockIdx.x * 256 + threadIdx.x) >> 5;
    int lane = threadIdx.x & 31;
    const float* src = (gw < NN) ? (X + (size_t)gw * KK) : (Y + (size_t)(gw - NN) * KK);
    float s = 0.f;
    #pragma unroll
    for (int c = 0; c < KK; c += 32) {
        float a = src[c + lane];
        s = fmaf(a, a, s);
    }
    #pragma unroll
    for (int o = 16; o; o >>= 1) s += __shfl_xor_sync(0xffffffffu, s, o);
    if (lane == 0) {
        if (gw < NN) g_xs[gw] = s; else g_ys[gw - NN] = s;
    }
}

__global__ void init_kernel() {
    int i = blockIdx.x * 256 + threadIdx.x;
    if (i < NN) { g_v[i] = 0.f; g_mu[i] = NEG_BIG; g_mv[i] = NEG_BIG; }
    if (i == 0) { g_bar_count = 0; g_bar_gen = 0; }
}

// ---------------------------------------------------------------------------
// C2[i][j] = (|x_i|^2 + |y_j|^2 - 2 x_i . y_j) * SCALEF  (fp32 FFMA GEMM)
__global__ __launch_bounds__(256) void gemm_kernel(const float* __restrict__ X,
                                                   const float* __restrict__ Y) {
    __shared__ float As[8][128];
    __shared__ float Bs[8][128];
    const int tid = threadIdx.x;
    const int bx = blockIdx.x;
    const int by = blockIdx.y;
    const int ar = tid >> 1;
    const int ak = (tid & 1) * 4;
    const int tx = tid & 15;
    const int ty = tid >> 4;

    const float* xp = X + (size_t)(by * 128 + ar) * KK + ak;
    const float* yp = Y + (size_t)(bx * 128 + ar) * KK + ak;

    float acc[8][8];
    #pragma unroll
    for (int i = 0; i < 8; ++i)
        #pragma unroll
        for (int j = 0; j < 8; ++j) acc[i][j] = 0.f;

    for (int kt = 0; kt < KK; kt += 8) {
        float4 av = *(const float4*)(xp + kt);
        float4 bv = *(const float4*)(yp + kt);
        __syncthreads();
        As[ak + 0][ar] = av.x; As[ak + 1][ar] = av.y;
        As[ak + 2][ar] = av.z; As[ak + 3][ar] = av.w;
        Bs[ak + 0][ar] = bv.x; Bs[ak + 1][ar] = bv.y;
        Bs[ak + 2][ar] = bv.z; Bs[ak + 3][ar] = bv.w;
        __syncthreads();
        #pragma unroll
        for (int k = 0; k < 8; ++k) {
            float a[8], b[8];
            *(float4*)(a)     = *(const float4*)&As[k][ty * 8];
            *(float4*)(a + 4) = *(const float4*)&As[k][ty * 8 + 4];
            *(float4*)(b)     = *(const float4*)&Bs[k][tx * 8];
            *(float4*)(b + 4) = *(const float4*)&Bs[k][tx * 8 + 4];
            #pragma unroll
            for (int i = 0; i < 8; ++i)
                #pragma unroll
                for (int j = 0; j < 8; ++j)
                    acc[i][j] = fmaf(a[i], b[j], acc[i][j]);
        }
    }

    const int gi0 = by * 128 + ty * 8;
    const int gj0 = bx * 128 + tx * 8;
    float yv[8];
    #pragma unroll
    for (int j = 0; j < 8; ++j) yv[j] = g_ys[gj0 + j];
    #pragma unroll
    for (int i = 0; i < 8; ++i) {
        float xs = g_xs[gi0 + i];
        float4 o0, o1;
        o0.x = (xs + yv[0] - 2.f * acc[i][0]) * SCALEF;
        o0.y = (xs + yv[1] - 2.f * acc[i][1]) * SCALEF;
        o0.z = (xs + yv[2] - 2.f * acc[i][2]) * SCALEF;
        o0.w = (xs + yv[3] - 2.f * acc[i][3]) * SCALEF;
        o1.x = (xs + yv[4] - 2.f * acc[i][4]) * SCALEF;
        o1.y = (xs + yv[5] - 2.f * acc[i][5]) * SCALEF;
        o1.z = (xs + yv[6] - 2.f * acc[i][6]) * SCALEF;
        o1.w = (xs + yv[7] - 2.f * acc[i][7]) * SCALEF;
        float* dst = g_C2 + (size_t)(gi0 + i) * NN + gj0;
        *(float4*)(dst)     = o0;
        *(float4*)(dst + 4) = o1;
    }
}

// ---------------------------------------------------------------------------
__global__ __launch_bounds__(THREADS, 1) void sinkhorn_persistent(int NB, float* __restrict__ out) {
    const int tid = threadIdx.x;
    const int bid = blockIdx.x;
    const int lane = tid & 31;
    const int wid = tid >> 5;

    __shared__ float svec[NN];          // 16 KB: dual-potential cache
    __shared__ float sm_m[32][33];
    __shared__ float sm_s[32][33];
    __shared__ float sshift[32];
    __shared__ int   sfail;
    __shared__ float sred[32];

    for (int it = 0; it < N_ITER; ++it) {
        // ---- u-pass: warp-per-row, lazy LSE ----
        for (int i = tid; i < NN; i += THREADS) svec[i] = g_v[i];
        __syncthreads();

        for (int row = bid + wid * NB; row < NN; row += 32 * NB) {
            const float* Crow = g_C2 + (size_t)row * NN;
            float shift = g_mu[row];
            float Mrun, Ssum;
            #pragma unroll 1
            for (int attempt = 0; attempt < 4; ++attempt) {
                float mrun = NEG_BIG, s = 0.f;
                const float thr = shift - TH_SKIP;
                #pragma unroll 1
                for (int c0 = 0; c0 < NN; c0 += 256) {
                    int c = c0 + lane * 4;
                    float4 C0 = __ldg((const float4*)(Crow + c));
                    float4 C1 = __ldg((const float4*)(Crow + c + 128));
                    float4 V0 = *(const float4*)&svec[c];
                    float4 V1 = *(const float4*)&svec[c + 128];
                    float t0 = V0.x - C0.x, t1 = V0.y - C0.y;
                    float t2 = V0.z - C0.z, t3 = V0.w - C0.w;
                    float t4 = V1.x - C1.x, t5 = V1.y - C1.y;
                    float t6 = V1.z - C1.z, t7 = V1.w - C1.w;
                    float mc = fmaxf(fmaxf(fmaxf(t0, t1), fmaxf(t2, t3)),
                                     fmaxf(fmaxf(t4, t5), fmaxf(t6, t7)));
                    mrun = fmaxf(mrun, mc);
                    if (__any_sync(0xffffffffu, mc >= thr)) {
                        s += ((ex2f(fminf(t0 - shift, CLAMP)) + ex2f(fminf(t1 - shift, CLAMP)))
                            + (ex2f(fminf(t2 - shift, CLAMP)) + ex2f(fminf(t3 - shift, CLAMP))))
                           + ((ex2f(fminf(t4 - shift, CLAMP)) + ex2f(fminf(t5 - shift, CLAMP)))
                            + (ex2f(fminf(t6 - shift, CLAMP)) + ex2f(fminf(t7 - shift, CLAMP))));
                    }
                }
                Mrun = mrun; Ssum = s;
                #pragma unroll
                for (int o = 16; o; o >>= 1) {
                    Mrun = fmaxf(Mrun, __shfl_xor_sync(0xffffffffu, Mrun, o));
                    Ssum += __shfl_xor_sync(0xffffffffu, Ssum, o);
                }
                if (Mrun >= shift - TH_LO && Mrun <= shift + TH_HI) break;
                shift = Mrun;
            }
            if (lane == 0) {
                g_u[row] = -(shift + lg2f(Ssum));
                g_mu[row] = Mrun;
            }
        }
        grid_sync(NB);

        // ---- v-pass: CTA owns 32 columns; lazy LSE; shift common per column ----
        for (int i = tid; i < NN; i += THREADS) svec[i] = g_u[i];
        __syncthreads();
        for (int g = bid; g < NN / 32; g += NB) {
            const int j0 = g << 5;
            const int c = lane;
            const int r = wid;
            if (tid < 32) sshift[tid] = g_mv[j0 + tid];
            if (tid == 0) sfail = 0;
            __syncthreads();
            #pragma unroll 1
            for (int attempt = 0; attempt < 4; ++attempt) {
                float shift = sshift[c];
                const float thr = shift - TH_SKIP;
                float mrun = NEG_BIG, s = 0.f;
                #pragma unroll 1
                for (int q0 = 0; q0 < NN; q0 += 512) {
                    const float* p = g_C2 + (size_t)(q0 + r) * NN + j0 + c;
                    const float* up = &svec[q0 + r];
                    float t[16];
                    #pragma unroll
                    for (int k = 0; k < 16; ++k)
                        t[k] = up[k << 5] - __ldg(p + ((size_t)k << 5) * NN);
                    float mc = t[0];
                    #pragma unroll
                    for (int k = 1; k < 16; ++k) mc = fmaxf(mc, t[k]);
                    mrun = fmaxf(mrun, mc);
                    if (__any_sync(0xffffffffu, mc >= thr)) {
                        float e = 0.f;
                        #pragma unroll
                        for (int k = 0; k < 16; ++k)
                            e += ex2f(fminf(t[k] - shift, CLAMP));
                        s += e;
                    }
                }
                sm_m[r][c] = mrun;
                sm_s[r][c] = s;
                __syncthreads();
                {   // warp wid merges column wid (plain sum: common shift)
                    float mm = sm_m[lane][wid];
                    float ss = sm_s[lane][wid];
                    #pragma unroll
                    for (int o = 16; o; o >>= 1) {
                        mm = fmaxf(mm, __shfl_xor_sync(0xffffffffu, mm, o));
                        ss += __shfl_xor_sync(0xffffffffu, ss, o);
                    }
                    float sc = sshift[wid];
                    bool ok = (mm >= sc - TH_LO && mm <= sc + TH_HI);
                    if (lane == 0) {
                        if (ok) {
                            g_v[j0 + wid] = -(sc + lg2f(ss));
                            g_mv[j0 + wid] = mm;
                        } else {
                            sshift[wid] = mm;
                            sfail = 1;
                        }
                    }
                }
                __syncthreads();
                if (!sfail) break;
                if (tid == 0) sfail = 0;
                __syncthreads();
            }
            __syncthreads();
        }
        grid_sync(NB);
    }

    // ---- final cost: sum P*C / N  (warp-per-row, full exp) ----
    {
        for (int i = tid; i < NN; i += THREADS) svec[i] = g_v[i];
        __syncthreads();
        float acc = 0.f;
        for (int row = bid + wid * NB; row < NN; row += 32 * NB) {
            const float u2 = g_u[row];
            const float* Crow = g_C2 + (size_t)row * NN;
            #pragma unroll 4
            for (int c0 = 0; c0 < NN; c0 += 128) {
                int cc = c0 + lane * 4;
                float4 C4 = __ldg((const float4*)(Crow + cc));
                float4 V4 = *(const float4*)&svec[cc];
                acc = fmaf(ex2f(u2 + V4.x - C4.x), C4.x, acc);
                acc = fmaf(ex2f(u2 + V4.y - C4.y), C4.y, acc);
                acc = fmaf(ex2f(u2 + V4.z - C4.z), C4.z, acc);
                acc = fmaf(ex2f(u2 + V4.w - C4.w), C4.w, acc);
            }
        }
        #pragma unroll
        for (int o = 16; o; o >>= 1) acc += __shfl_xor_sync(0xffffffffu, acc, o);
        __syncthreads();
        if (lane == 0) sred[wid] = acc;
        __syncthreads();
        if (wid == 0) {
            float s = sred[lane];
            #pragma unroll
            for (int o = 16; o; o >>= 1) s += __shfl_xor_sync(0xffffffffu, s, o);
            if (lane == 0) g_dpart[bid] = (double)s;
        }
        grid_sync(NB);
        if (bid == 0 && tid == 0) {
            double S = 0.0;
            for (int b = 0; b < NB; ++b) S += g_dpart[b];
            out[0] = (float)(S / ((double)SCALEF * (double)NN));
        }
    }
}

// ---------------------------------------------------------------------------
extern "C" void kernel_launch(void* const* d_in, const int* in_sizes, int n_in,
                              void* d_out, int out_size) {
    const float* x = (const float*)d_in[0];
    const float* y = (const float*)d_in[1];
    float* out = (float*)d_out;

    int dev = 0;
    cudaGetDevice(&dev);
    int sm = 148;
    cudaDeviceGetAttribute(&sm, cudaDevAttrMultiProcessorCount, dev);
    int NB = sm < NBMAX ? sm : NBMAX;

    sqnorm_kernel<<<1024, 256>>>(x, y);
    init_kernel<<<16, 256>>>();
    gemm_kernel<<<dim3(32, 32), 256>>>(x, y);
    sinkhorn_persistent<<<NB, THREADS>>>(NB, out);
}